// round 4
// baseline (speedup 1.0000x reference)
#include <cuda_runtime.h>
#include <math.h>
#include <float.h>

#define NPTS 16384
#define HID  256
#define KTOT 384                 // stacked K = 256 + 128
#define KNN  7                   // k+1 smallest kept per row

// ---- spatial grid ----
#define GRIDW   256
#define NCELLS  (GRIDW * GRIDW)
#define CELL    0.5f
#define INV_CELL 2.0f
#define ORIGINF (-64.0f)

// Scratch (device globals; no allocation allowed)
__device__ int    g_cnt[NCELLS];
__device__ int    g_start[NCELLS + 1];
__device__ int    g_write[NCELLS];
__device__ float2 g_pts[NPTS];       // points in cell-sorted order
__device__ int    g_sid[NPTS];       // original index per sorted slot
__device__ float  g_mean[NPTS];      // mean kNN distance per row
__device__ float  g_A[NPTS * KTOT];  // stacked activations [h | u]

// ---------------------------------------------------------------------------
__device__ __forceinline__ void cell_of(float x, float y, int& cx, int& cy) {
    cx = min(max(__float2int_rd((x - ORIGINF) * INV_CELL), 0), GRIDW - 1);
    cy = min(max(__float2int_rd((y - ORIGINF) * INV_CELL), 0), GRIDW - 1);
}

__global__ void zero_counts() {
    int i = blockIdx.x * 1024 + threadIdx.x;
    if (i < NCELLS) g_cnt[i] = 0;
}

__global__ void count_pts(const float2* __restrict__ coords) {
    int i = blockIdx.x * 1024 + threadIdx.x;
    if (i >= NPTS) return;
    float2 c = coords[i];
    int cx, cy;
    cell_of(c.x, c.y, cx, cy);
    atomicAdd(&g_cnt[cy * GRIDW + cx], 1);
}

// single-block exclusive scan of 65536 counts (64 cells per thread)
__global__ void __launch_bounds__(1024) scan_counts() {
    __shared__ int ps[1024];
    int t = threadIdx.x;
    int base = t * 64;
    int sum = 0;
#pragma unroll 4
    for (int c = 0; c < 64; ++c) sum += g_cnt[base + c];
    ps[t] = sum;
    __syncthreads();
    for (int off = 1; off < 1024; off <<= 1) {
        int v = (t >= off) ? ps[t - off] : 0;
        __syncthreads();
        ps[t] += v;
        __syncthreads();
    }
    int run = ps[t] - sum;   // exclusive prefix of this thread's chunk
#pragma unroll 4
    for (int c = 0; c < 64; ++c) {
        int cnt = g_cnt[base + c];
        g_start[base + c] = run;
        g_write[base + c] = run;
        run += cnt;
    }
    if (t == 1023) g_start[NCELLS] = run;
}

__global__ void scatter_pts(const float2* __restrict__ coords) {
    int i = blockIdx.x * 1024 + threadIdx.x;
    if (i >= NPTS) return;
    float2 c = coords[i];
    int cx, cy;
    cell_of(c.x, c.y, cx, cy);
    int pos = atomicAdd(&g_write[cy * GRIDW + cx], 1);
    g_pts[pos] = c;
    g_sid[pos] = i;
}

// ---------------------------------------------------------------------------
// Exact kNN via expanding Chebyshev rings. Ring r (r>=1) holds only points at
// distance >= (r-1)*CELL from the query, so once best[6] < ((r-1)*CELL)^2 we
// can stop before scanning ring r. Queries run in cell-sorted order so warps
// stay spatially coherent.
// ---------------------------------------------------------------------------
#define INSERT7(d2)                                              \
    do {                                                          \
        best[6] = (d2);                                           \
        float lo, hi;                                             \
        lo = fminf(best[5], best[6]); hi = fmaxf(best[5], best[6]); best[5] = lo; best[6] = hi; \
        lo = fminf(best[4], best[5]); hi = fmaxf(best[4], best[5]); best[4] = lo; best[5] = hi; \
        lo = fminf(best[3], best[4]); hi = fmaxf(best[3], best[4]); best[3] = lo; best[4] = hi; \
        lo = fminf(best[2], best[3]); hi = fmaxf(best[2], best[3]); best[2] = lo; best[3] = hi; \
        lo = fminf(best[1], best[2]); hi = fmaxf(best[1], best[2]); best[1] = lo; best[2] = hi; \
        lo = fminf(best[0], best[1]); hi = fmaxf(best[0], best[1]); best[0] = lo; best[1] = hi; \
    } while (0)

#define VISIT(CX, CY)                                             \
    do {                                                          \
        int cid = (CY) * GRIDW + (CX);                            \
        int st = g_start[cid];                                    \
        int en = g_start[cid + 1];                                \
        for (int p = st; p < en; ++p) {                           \
            float2 pt = g_pts[p];                                 \
            float dx = pt.x - qx;                                 \
            float dy = pt.y - qy;                                 \
            float d2 = fmaf(dx, dx, dy * dy);                     \
            if (d2 < best[6]) { INSERT7(d2); }                    \
        }                                                         \
    } while (0)

__global__ void __launch_bounds__(256) query_knn() {
    int i = blockIdx.x * 256 + threadIdx.x;
    if (i >= NPTS) return;
    float2 q = g_pts[i];
    int orig = g_sid[i];
    float qx = q.x, qy = q.y;

    float best[KNN];
#pragma unroll
    for (int t = 0; t < KNN; ++t) best[t] = FLT_MAX;

    int cx, cy;
    cell_of(qx, qy, cx, cy);

    for (int r = 0; r <= GRIDW; ++r) {
        if (r > 0) {
            float bound = (float)(r - 1) * CELL;
            if (best[6] < bound * bound) break;
        }
        if (r == 0) {
            VISIT(cx, cy);
        } else {
            int x0 = cx - r, x1 = cx + r, y0 = cy - r, y1 = cy + r;
            int xa = max(x0, 0), xb = min(x1, GRIDW - 1);
            for (int x = xa; x <= xb; ++x) {
                if (y0 >= 0)     VISIT(x, y0);
                if (y1 < GRIDW)  VISIT(x, y1);
            }
            int ya = max(y0 + 1, 0), yb = min(y1 - 1, GRIDW - 1);
            for (int y = ya; y <= yb; ++y) {
                if (x0 >= 0)     VISIT(x0, y);
                if (x1 < GRIDW)  VISIT(x1, y);
            }
        }
    }

    // entries 1..6 (entry 0 is self at ~0); ascending order -> deterministic sum
    float sum = 0.f;
#pragma unroll
    for (int t = 1; t < KNN; ++t)
        sum += sqrtf(fmaxf(best[t], 1e-12f));
    g_mean[orig] = sum * (1.f / (float)(KNN - 1));
}

// ---------------------------------------------------------------------------
// Build stacked activations A[row] = [ silu(x@W1+b1) | silu(m@Wd1+bd1) ]
// ---------------------------------------------------------------------------
__global__ void __launch_bounds__(KTOT) build_A(const float2* __restrict__ coords,
                                                const float* __restrict__ W1,
                                                const float* __restrict__ b1,
                                                const float* __restrict__ Wd1,
                                                const float* __restrict__ bd1) {
    int row = blockIdx.x;
    int k   = threadIdx.x;
    float z;
    if (k < HID) {
        float2 q = coords[row];
        z = fmaf(q.x, W1[k], fmaf(q.y, W1[HID + k], b1[k]));
    } else {
        int   kd = k - HID;
        float m  = g_mean[row];
        z = fmaf(m, Wd1[kd], bd1[kd]);
    }
    float sil = z / (1.f + __expf(-z));
    g_A[row * KTOT + k] = sil;
}

// ---------------------------------------------------------------------------
// out = A @ [W2; Wd2] + (b2 + bd2)
// M=16384, N=256, K=384. BM=128, BN=64, BK=32, 128 threads, 8x8 per thread,
// 3 blocks/SM target.
// As padded to stride 33: scalar aReg loads hit 4 distinct banks (m0 in
// {0,8,16,24}) -> conflict-free; scalar A-stores cover all 32 banks.
// ---------------------------------------------------------------------------
__global__ void __launch_bounds__(128, 3) gemm_pass(const float* __restrict__ W2,
                                                    const float* __restrict__ b2,
                                                    const float* __restrict__ Wd2,
                                                    const float* __restrict__ bd2,
                                                    float* __restrict__ out) {
    __shared__ float As[128][33];
    __shared__ float Bs[32][64];

    int bn  = blockIdx.x;    // 0..3
    int bm  = blockIdx.y;    // 0..127
    int tid = threadIdx.x;

    int m0 = (tid >> 3) * 8;   // 0..120
    int n0 = (tid & 7) * 8;    // 0..56

    int rowBase = bm * 128;
    int nBase   = bn * 64;

    // A-load mapping: 8 x float4 per thread (coalesced: 8 lanes x 16B per row)
    int am = tid >> 3;          // 0..15
    int ak = (tid & 7) * 4;     // 0..28
    // B-load mapping: 4 x float4 per thread (coalesced: 16 lanes x 16B per row)
    int bk  = tid >> 4;         // 0..7
    int bn4 = (tid & 15) * 4;   // 0..60

    float acc[8][8];
#pragma unroll
    for (int i = 0; i < 8; ++i)
#pragma unroll
        for (int j = 0; j < 8; ++j) acc[i][j] = 0.f;

    for (int kt = 0; kt < KTOT; kt += 32) {
#pragma unroll
        for (int i = 0; i < 8; ++i) {
            int m = am + i * 16;
            float4 v = *(const float4*)&g_A[(rowBase + m) * KTOT + kt + ak];
            As[m][ak + 0] = v.x;
            As[m][ak + 1] = v.y;
            As[m][ak + 2] = v.z;
            As[m][ak + 3] = v.w;
        }
#pragma unroll
        for (int i = 0; i < 4; ++i) {
            int kk    = bk + i * 8;
            int kglob = kt + kk;
            const float* src = (kglob < HID)
                                   ? &W2[kglob * HID + nBase + bn4]
                                   : &Wd2[(kglob - HID) * HID + nBase + bn4];
            *(float4*)&Bs[kk][bn4] = *(const float4*)src;
        }
        __syncthreads();

#pragma unroll
        for (int kk = 0; kk < 32; ++kk) {
            float aReg[8], bReg[8];
#pragma unroll
            for (int i = 0; i < 8; ++i) aReg[i] = As[m0 + i][kk];
            *(float4*)&bReg[0] = *(const float4*)&Bs[kk][n0];
            *(float4*)&bReg[4] = *(const float4*)&Bs[kk][n0 + 4];
#pragma unroll
            for (int i = 0; i < 8; ++i)
#pragma unroll
                for (int j = 0; j < 8; ++j)
                    acc[i][j] = fmaf(aReg[i], bReg[j], acc[i][j]);
        }
        __syncthreads();
    }

#pragma unroll
    for (int i = 0; i < 8; ++i) {
        int row = rowBase + m0 + i;
#pragma unroll
        for (int j4 = 0; j4 < 2; ++j4) {
            int n = nBase + n0 + j4 * 4;
            float4 o;
            o.x = acc[i][j4 * 4 + 0] + b2[n + 0] + bd2[n + 0];
            o.y = acc[i][j4 * 4 + 1] + b2[n + 1] + bd2[n + 1];
            o.z = acc[i][j4 * 4 + 2] + b2[n + 2] + bd2[n + 2];
            o.w = acc[i][j4 * 4 + 3] + b2[n + 3] + bd2[n + 3];
            *(float4*)&out[row * HID + n] = o;
        }
    }
}

// ---------------------------------------------------------------------------
extern "C" void kernel_launch(void* const* d_in, const int* in_sizes, int n_in,
                              void* d_out, int out_size) {
    (void)in_sizes; (void)n_in; (void)out_size;
    const float2* coords = (const float2*)d_in[0];
    const float*  W1  = (const float*)d_in[1];
    const float*  b1  = (const float*)d_in[2];
    const float*  W2  = (const float*)d_in[3];
    const float*  b2  = (const float*)d_in[4];
    const float*  Wd1 = (const float*)d_in[5];
    const float*  bd1 = (const float*)d_in[6];
    const float*  Wd2 = (const float*)d_in[7];
    const float*  bd2 = (const float*)d_in[8];
    float* out = (float*)d_out;

    zero_counts<<<NCELLS / 1024, 1024>>>();
    count_pts<<<NPTS / 1024, 1024>>>(coords);
    scan_counts<<<1, 1024>>>();
    scatter_pts<<<NPTS / 1024, 1024>>>(coords);
    query_knn<<<NPTS / 256, 256>>>();
    build_A<<<NPTS, KTOT>>>(coords, W1, b1, Wd1, bd1);
    gemm_pass<<<dim3(4, 128), 128>>>(W2, b2, Wd2, bd2, out);
}

// round 6
// speedup vs baseline: 2.2844x; 2.2844x over previous
#include <cuda_runtime.h>
#include <math.h>
#include <float.h>

#define NPTS 16384
#define HID  256
#define KTOT 384                 // stacked K = 256 + 128
#define KNN  7                   // k+1 smallest kept per row

// ---- spatial grid ----
#define GRIDW   128
#define NCELLS  (GRIDW * GRIDW)
#define CELL    1.0f
#define INV_CELL 1.0f
#define ORIGINF (-64.0f)
#define R_MAX   3

// Scratch (device globals; no allocation allowed)
__device__ int    g_cnt[NCELLS];
__device__ int    g_start[NCELLS + 1];
__device__ int    g_write[NCELLS];
__device__ float2 g_pts[NPTS];       // points in cell-sorted order
__device__ int    g_sid[NPTS];       // original index per sorted slot
__device__ float  g_mean[NPTS];      // mean kNN distance per row
__device__ float  g_A[NPTS * KTOT];  // stacked activations [h | u]
__device__ int    g_fb[NPTS];        // fallback query slots (sorted index)
__device__ int    g_fbcnt;

// ---------------------------------------------------------------------------
__device__ __forceinline__ void cell_of(float x, float y, int& cx, int& cy) {
    cx = min(max(__float2int_rd((x - ORIGINF) * INV_CELL), 0), GRIDW - 1);
    cy = min(max(__float2int_rd((y - ORIGINF) * INV_CELL), 0), GRIDW - 1);
}

__global__ void zero_counts() {
    int i = blockIdx.x * 1024 + threadIdx.x;
    if (i < NCELLS) g_cnt[i] = 0;
    if (i == 0) g_fbcnt = 0;
}

__global__ void count_pts(const float2* __restrict__ coords) {
    int i = blockIdx.x * 1024 + threadIdx.x;
    if (i >= NPTS) return;
    float2 c = coords[i];
    int cx, cy;
    cell_of(c.x, c.y, cx, cy);
    atomicAdd(&g_cnt[cy * GRIDW + cx], 1);
}

// single-block exclusive scan of NCELLS counts (16 cells per thread)
__global__ void __launch_bounds__(1024) scan_counts() {
    __shared__ int ps[1024];
    int t = threadIdx.x;
    int base = t * (NCELLS / 1024);
    int sum = 0;
#pragma unroll
    for (int c = 0; c < NCELLS / 1024; ++c) sum += g_cnt[base + c];
    ps[t] = sum;
    __syncthreads();
    for (int off = 1; off < 1024; off <<= 1) {
        int v = (t >= off) ? ps[t - off] : 0;
        __syncthreads();
        ps[t] += v;
        __syncthreads();
    }
    int run = ps[t] - sum;
#pragma unroll
    for (int c = 0; c < NCELLS / 1024; ++c) {
        int cnt = g_cnt[base + c];
        g_start[base + c] = run;
        g_write[base + c] = run;
        run += cnt;
    }
    if (t == 1023) g_start[NCELLS] = run;
}

__global__ void scatter_pts(const float2* __restrict__ coords) {
    int i = blockIdx.x * 1024 + threadIdx.x;
    if (i >= NPTS) return;
    float2 c = coords[i];
    int cx, cy;
    cell_of(c.x, c.y, cx, cy);
    int pos = atomicAdd(&g_write[cy * GRIDW + cx], 1);
    g_pts[pos] = c;
    g_sid[pos] = i;
}

// ---------------------------------------------------------------------------
#define INSERT7(B, d2)                                            \
    do {                                                          \
        (B)[6] = (d2);                                            \
        float lo, hi;                                             \
        lo = fminf((B)[5], (B)[6]); hi = fmaxf((B)[5], (B)[6]); (B)[5] = lo; (B)[6] = hi; \
        lo = fminf((B)[4], (B)[5]); hi = fmaxf((B)[4], (B)[5]); (B)[4] = lo; (B)[5] = hi; \
        lo = fminf((B)[3], (B)[4]); hi = fmaxf((B)[3], (B)[4]); (B)[3] = lo; (B)[4] = hi; \
        lo = fminf((B)[2], (B)[3]); hi = fmaxf((B)[2], (B)[3]); (B)[2] = lo; (B)[3] = hi; \
        lo = fminf((B)[1], (B)[2]); hi = fmaxf((B)[1], (B)[2]); (B)[1] = lo; (B)[2] = hi; \
        lo = fminf((B)[0], (B)[1]); hi = fmaxf((B)[0], (B)[1]); (B)[0] = lo; (B)[1] = hi; \
    } while (0)

// Scan one contiguous run of cells in a row: cells [XA..XB] in row CY.
// Row-major cell sort => their point ranges are contiguous.
#define VISIT_RANGE(XA, XB, CY)                                   \
    do {                                                          \
        int st = g_start[(CY) * GRIDW + (XA)];                    \
        int en = g_start[(CY) * GRIDW + (XB) + 1];                \
        for (int p = st; p < en; ++p) {                           \
            float2 pt = g_pts[p];                                 \
            float dx = pt.x - qx;                                 \
            float dy = pt.y - qy;                                 \
            float d2 = fmaf(dx, dx, dy * dy);                     \
            if (d2 < best[6]) { INSERT7(best, d2); }              \
        }                                                         \
    } while (0)

// ---------------------------------------------------------------------------
// Budgeted exact kNN: rings 0..R_MAX, early-terminated; unresolved queries
// (Gaussian tail, ~1%) go to a fallback list for warp-parallel brute force.
// ---------------------------------------------------------------------------
__global__ void __launch_bounds__(256) query_knn() {
    int i = blockIdx.x * 256 + threadIdx.x;
    if (i >= NPTS) return;
    float2 q = g_pts[i];
    int orig = g_sid[i];
    float qx = q.x, qy = q.y;

    float best[KNN];
#pragma unroll
    for (int t = 0; t < KNN; ++t) best[t] = FLT_MAX;

    int cx, cy;
    cell_of(qx, qy, cx, cy);

    bool resolved = false;
#pragma unroll
    for (int r = 0; r <= R_MAX; ++r) {
        if (r > 0) {
            float bound = (float)(r - 1) * CELL;
            if (best[6] < bound * bound) { resolved = true; break; }
        }
        if (r == 0) {
            VISIT_RANGE(cx, cx, cy);
        } else {
            int xa = max(cx - r, 0), xb = min(cx + r, GRIDW - 1);
            int y0 = cy - r, y1 = cy + r;
            if (y0 >= 0)    VISIT_RANGE(xa, xb, y0);
            if (y1 < GRIDW) VISIT_RANGE(xa, xb, y1);
            int ya = max(y0 + 1, 0), yb = min(y1 - 1, GRIDW - 1);
            int xl = cx - r, xr = cx + r;
            for (int y = ya; y <= yb; ++y) {
                if (xl >= 0)    VISIT_RANGE(xl, xl, y);
                if (xr < GRIDW) VISIT_RANGE(xr, xr, y);
            }
        }
    }
    if (!resolved) {
        float bound = (float)R_MAX * CELL;   // ring R_MAX+1 pts are >= this far
        resolved = best[6] < bound * bound;
    }

    if (resolved) {
        float sum = 0.f;
#pragma unroll
        for (int t = 1; t < KNN; ++t)
            sum += sqrtf(fmaxf(best[t], 1e-12f));
        g_mean[orig] = sum * (1.f / (float)(KNN - 1));
    } else {
        int slot = atomicAdd(&g_fbcnt, 1);
        g_fb[slot] = i;   // sorted-slot index
    }
}

// ---------------------------------------------------------------------------
// Fallback: one warp per unresolved query, brute force over all points.
// ---------------------------------------------------------------------------
__global__ void __launch_bounds__(256) fb_knn() {
    int nfb = g_fbcnt;
    int lane = threadIdx.x & 31;
    int gwarp = blockIdx.x * 8 + (threadIdx.x >> 5);
    int nwarp = gridDim.x * 8;

    for (int qi = gwarp; qi < nfb; qi += nwarp) {
        int slot = g_fb[qi];
        float2 q = g_pts[slot];
        int orig = g_sid[slot];
        float qx = q.x, qy = q.y;

        float best[KNN];
#pragma unroll
        for (int t = 0; t < KNN; ++t) best[t] = FLT_MAX;

#pragma unroll 4
        for (int j = lane; j < NPTS; j += 32) {
            float2 pt = g_pts[j];
            float dx = pt.x - qx;
            float dy = pt.y - qy;
            float d2 = fmaf(dx, dx, dy * dy);
            if (d2 < best[6]) { INSERT7(best, d2); }
        }

        // warp merge: 7 rounds of argmin over each lane's sorted head
        float res[KNN];
#pragma unroll
        for (int t = 0; t < KNN; ++t) {
            float m = best[0];
            int ml = lane;
#pragma unroll
            for (int off = 16; off > 0; off >>= 1) {
                float ov = __shfl_xor_sync(0xffffffffu, m, off);
                int   ol = __shfl_xor_sync(0xffffffffu, ml, off);
                if (ov < m || (ov == m && ol < ml)) { m = ov; ml = ol; }
            }
            res[t] = m;
            if (lane == ml) {
                best[0] = best[1]; best[1] = best[2]; best[2] = best[3];
                best[3] = best[4]; best[4] = best[5]; best[5] = best[6];
                best[6] = FLT_MAX;
            }
        }

        if (lane == 0) {
            float sum = 0.f;
#pragma unroll
            for (int t = 1; t < KNN; ++t)
                sum += sqrtf(fmaxf(res[t], 1e-12f));
            g_mean[orig] = sum * (1.f / (float)(KNN - 1));
        }
    }
}

// ---------------------------------------------------------------------------
// Build stacked activations A[row] = [ silu(x@W1+b1) | silu(m@Wd1+bd1) ]
// ---------------------------------------------------------------------------
__global__ void __launch_bounds__(KTOT) build_A(const float2* __restrict__ coords,
                                                const float* __restrict__ W1,
                                                const float* __restrict__ b1,
                                                const float* __restrict__ Wd1,
                                                const float* __restrict__ bd1) {
    int row = blockIdx.x;
    int k   = threadIdx.x;
    float z;
    if (k < HID) {
        float2 q = coords[row];
        z = fmaf(q.x, W1[k], fmaf(q.y, W1[HID + k], b1[k]));
    } else {
        int   kd = k - HID;
        float m  = g_mean[row];
        z = fmaf(m, Wd1[kd], bd1[kd]);
    }
    float sil = z / (1.f + __expf(-z));
    g_A[row * KTOT + k] = sil;
}

// ---------------------------------------------------------------------------
// out = A @ [W2; Wd2] + (b2 + bd2)
// M=16384, N=256, K=384. BM=128, BN=64, BK=32, 128 threads, 8x8 per thread.
// ---------------------------------------------------------------------------
__global__ void __launch_bounds__(128, 3) gemm_pass(const float* __restrict__ W2,
                                                    const float* __restrict__ b2,
                                                    const float* __restrict__ Wd2,
                                                    const float* __restrict__ bd2,
                                                    float* __restrict__ out) {
    __shared__ float As[128][33];
    __shared__ float Bs[32][64];

    int bn  = blockIdx.x;
    int bm  = blockIdx.y;
    int tid = threadIdx.x;

    int m0 = (tid >> 3) * 8;
    int n0 = (tid & 7) * 8;

    int rowBase = bm * 128;
    int nBase   = bn * 64;

    int am = tid >> 3;
    int ak = (tid & 7) * 4;
    int bk  = tid >> 4;
    int bn4 = (tid & 15) * 4;

    float acc[8][8];
#pragma unroll
    for (int i = 0; i < 8; ++i)
#pragma unroll
        for (int j = 0; j < 8; ++j) acc[i][j] = 0.f;

    for (int kt = 0; kt < KTOT; kt += 32) {
#pragma unroll
        for (int i = 0; i < 8; ++i) {
            int m = am + i * 16;
            float4 v = *(const float4*)&g_A[(rowBase + m) * KTOT + kt + ak];
            As[m][ak + 0] = v.x;
            As[m][ak + 1] = v.y;
            As[m][ak + 2] = v.z;
            As[m][ak + 3] = v.w;
        }
#pragma unroll
        for (int i = 0; i < 4; ++i) {
            int kk    = bk + i * 8;
            int kglob = kt + kk;
            const float* src = (kglob < HID)
                                   ? &W2[kglob * HID + nBase + bn4]
                                   : &Wd2[(kglob - HID) * HID + nBase + bn4];
            *(float4*)&Bs[kk][bn4] = *(const float4*)src;
        }
        __syncthreads();

#pragma unroll
        for (int kk = 0; kk < 32; ++kk) {
            float aReg[8], bReg[8];
#pragma unroll
            for (int i = 0; i < 8; ++i) aReg[i] = As[m0 + i][kk];
            *(float4*)&bReg[0] = *(const float4*)&Bs[kk][n0];
            *(float4*)&bReg[4] = *(const float4*)&Bs[kk][n0 + 4];
#pragma unroll
            for (int i = 0; i < 8; ++i)
#pragma unroll
                for (int j = 0; j < 8; ++j)
                    acc[i][j] = fmaf(aReg[i], bReg[j], acc[i][j]);
        }
        __syncthreads();
    }

#pragma unroll
    for (int i = 0; i < 8; ++i) {
        int row = rowBase + m0 + i;
#pragma unroll
        for (int j4 = 0; j4 < 2; ++j4) {
            int n = nBase + n0 + j4 * 4;
            float4 o;
            o.x = acc[i][j4 * 4 + 0] + b2[n + 0] + bd2[n + 0];
            o.y = acc[i][j4 * 4 + 1] + b2[n + 1] + bd2[n + 1];
            o.z = acc[i][j4 * 4 + 2] + b2[n + 2] + bd2[n + 2];
            o.w = acc[i][j4 * 4 + 3] + b2[n + 3] + bd2[n + 3];
            *(float4*)&out[row * HID + n] = o;
        }
    }
}

// ---------------------------------------------------------------------------
extern "C" void kernel_launch(void* const* d_in, const int* in_sizes, int n_in,
                              void* d_out, int out_size) {
    (void)in_sizes; (void)n_in; (void)out_size;
    const float2* coords = (const float2*)d_in[0];
    const float*  W1  = (const float*)d_in[1];
    const float*  b1  = (const float*)d_in[2];
    const float*  W2  = (const float*)d_in[3];
    const float*  b2  = (const float*)d_in[4];
    const float*  Wd1 = (const float*)d_in[5];
    const float*  bd1 = (const float*)d_in[6];
    const float*  Wd2 = (const float*)d_in[7];
    const float*  bd2 = (const float*)d_in[8];
    float* out = (float*)d_out;

    zero_counts<<<NCELLS / 1024, 1024>>>();
    count_pts<<<NPTS / 1024, 1024>>>(coords);
    scan_counts<<<1, 1024>>>();
    scatter_pts<<<NPTS / 1024, 1024>>>(coords);
    query_knn<<<NPTS / 256, 256>>>();
    fb_knn<<<64, 256>>>();
    build_A<<<NPTS, KTOT>>>(coords, W1, b1, Wd1, bd1);
    gemm_pass<<<dim3(4, 128), 128>>>(W2, b2, Wd2, bd2, out);
}

// round 7
// speedup vs baseline: 2.5150x; 1.1009x over previous
#include <cuda_runtime.h>
#include <math.h>
#include <float.h>

#define NPTS 16384
#define HID  256
#define KTOT 384                 // stacked K = 256 + 128
#define KNN  7                   // k+1 smallest kept per row

// ---- spatial grid ----
#define GRIDW   128
#define NCELLS  (GRIDW * GRIDW)
#define CELL    1.0f
#define INV_CELL 1.0f
#define ORIGINF (-64.0f)
#define R_MAX   3

// Scratch (device globals; no allocation allowed)
__device__ int    g_cnt[NCELLS];
__device__ int    g_start[NCELLS + 1];
__device__ int    g_write[NCELLS];
__device__ float2 g_pts[NPTS];       // points in cell-sorted order
__device__ int    g_sid[NPTS];       // original index per sorted slot
__device__ float  g_mean[NPTS];      // mean kNN distance per row
__device__ float  g_A[NPTS * KTOT];  // stacked activations [h | u]
__device__ int    g_fb[NPTS];        // fallback query slots (sorted index)
__device__ int    g_fbcnt;

// ---------------------------------------------------------------------------
__device__ __forceinline__ void cell_of(float x, float y, int& cx, int& cy) {
    cx = min(max(__float2int_rd((x - ORIGINF) * INV_CELL), 0), GRIDW - 1);
    cy = min(max(__float2int_rd((y - ORIGINF) * INV_CELL), 0), GRIDW - 1);
}

__global__ void zero_counts() {
    int i = blockIdx.x * 1024 + threadIdx.x;
    if (i < NCELLS) g_cnt[i] = 0;
    if (i == 0) g_fbcnt = 0;
}

__global__ void count_pts(const float2* __restrict__ coords) {
    int i = blockIdx.x * 1024 + threadIdx.x;
    if (i >= NPTS) return;
    float2 c = coords[i];
    int cx, cy;
    cell_of(c.x, c.y, cx, cy);
    atomicAdd(&g_cnt[cy * GRIDW + cx], 1);
}

// single-block exclusive scan of NCELLS counts (16 cells per thread)
__global__ void __launch_bounds__(1024) scan_counts() {
    __shared__ int ps[1024];
    int t = threadIdx.x;
    int base = t * (NCELLS / 1024);
    int sum = 0;
#pragma unroll
    for (int c = 0; c < NCELLS / 1024; ++c) sum += g_cnt[base + c];
    ps[t] = sum;
    __syncthreads();
    for (int off = 1; off < 1024; off <<= 1) {
        int v = (t >= off) ? ps[t - off] : 0;
        __syncthreads();
        ps[t] += v;
        __syncthreads();
    }
    int run = ps[t] - sum;
#pragma unroll
    for (int c = 0; c < NCELLS / 1024; ++c) {
        int cnt = g_cnt[base + c];
        g_start[base + c] = run;
        g_write[base + c] = run;
        run += cnt;
    }
    if (t == 1023) g_start[NCELLS] = run;
}

__global__ void scatter_pts(const float2* __restrict__ coords) {
    int i = blockIdx.x * 1024 + threadIdx.x;
    if (i >= NPTS) return;
    float2 c = coords[i];
    int cx, cy;
    cell_of(c.x, c.y, cx, cy);
    int pos = atomicAdd(&g_write[cy * GRIDW + cx], 1);
    g_pts[pos] = c;
    g_sid[pos] = i;
}

// ---------------------------------------------------------------------------
#define INSERT7(B, d2)                                            \
    do {                                                          \
        (B)[6] = (d2);                                            \
        float lo, hi;                                             \
        lo = fminf((B)[5], (B)[6]); hi = fmaxf((B)[5], (B)[6]); (B)[5] = lo; (B)[6] = hi; \
        lo = fminf((B)[4], (B)[5]); hi = fmaxf((B)[4], (B)[5]); (B)[4] = lo; (B)[5] = hi; \
        lo = fminf((B)[3], (B)[4]); hi = fmaxf((B)[3], (B)[4]); (B)[3] = lo; (B)[4] = hi; \
        lo = fminf((B)[2], (B)[3]); hi = fmaxf((B)[2], (B)[3]); (B)[2] = lo; (B)[3] = hi; \
        lo = fminf((B)[1], (B)[2]); hi = fmaxf((B)[1], (B)[2]); (B)[1] = lo; (B)[2] = hi; \
        lo = fminf((B)[0], (B)[1]); hi = fmaxf((B)[0], (B)[1]); (B)[0] = lo; (B)[1] = hi; \
    } while (0)

// Scan one contiguous run of cells in a row: cells [XA..XB] in row CY.
// Row-major cell sort => their point ranges are contiguous.
#define VISIT_RANGE(XA, XB, CY)                                   \
    do {                                                          \
        int st = g_start[(CY) * GRIDW + (XA)];                    \
        int en = g_start[(CY) * GRIDW + (XB) + 1];                \
        for (int p = st; p < en; ++p) {                           \
            float2 pt = g_pts[p];                                 \
            float dx = pt.x - qx;                                 \
            float dy = pt.y - qy;                                 \
            float d2 = fmaf(dx, dx, dy * dy);                     \
            if (d2 < best[6]) { INSERT7(best, d2); }              \
        }                                                         \
    } while (0)

// ---------------------------------------------------------------------------
// Budgeted exact kNN: rings 0..R_MAX, early-terminated; unresolved queries
// (Gaussian tail, ~1%) go to a fallback list for warp-parallel brute force.
// ---------------------------------------------------------------------------
__global__ void __launch_bounds__(256) query_knn() {
    int i = blockIdx.x * 256 + threadIdx.x;
    if (i >= NPTS) return;
    float2 q = g_pts[i];
    int orig = g_sid[i];
    float qx = q.x, qy = q.y;

    float best[KNN];
#pragma unroll
    for (int t = 0; t < KNN; ++t) best[t] = FLT_MAX;

    int cx, cy;
    cell_of(qx, qy, cx, cy);

    bool resolved = false;
#pragma unroll
    for (int r = 0; r <= R_MAX; ++r) {
        if (r > 0) {
            float bound = (float)(r - 1) * CELL;
            if (best[6] < bound * bound) { resolved = true; break; }
        }
        if (r == 0) {
            VISIT_RANGE(cx, cx, cy);
        } else {
            int xa = max(cx - r, 0), xb = min(cx + r, GRIDW - 1);
            int y0 = cy - r, y1 = cy + r;
            if (y0 >= 0)    VISIT_RANGE(xa, xb, y0);
            if (y1 < GRIDW) VISIT_RANGE(xa, xb, y1);
            int ya = max(y0 + 1, 0), yb = min(y1 - 1, GRIDW - 1);
            int xl = cx - r, xr = cx + r;
            for (int y = ya; y <= yb; ++y) {
                if (xl >= 0)    VISIT_RANGE(xl, xl, y);
                if (xr < GRIDW) VISIT_RANGE(xr, xr, y);
            }
        }
    }
    if (!resolved) {
        float bound = (float)R_MAX * CELL;   // ring R_MAX+1 pts are >= this far
        resolved = best[6] < bound * bound;
    }

    if (resolved) {
        float sum = 0.f;
#pragma unroll
        for (int t = 1; t < KNN; ++t)
            sum += sqrtf(fmaxf(best[t], 1e-12f));
        g_mean[orig] = sum * (1.f / (float)(KNN - 1));
    } else {
        int slot = atomicAdd(&g_fbcnt, 1);
        g_fb[slot] = i;   // sorted-slot index
    }
}

// ---------------------------------------------------------------------------
// Fallback: one warp per unresolved query, brute force over all points.
// ---------------------------------------------------------------------------
__global__ void __launch_bounds__(256) fb_knn() {
    int nfb = g_fbcnt;
    int lane = threadIdx.x & 31;
    int gwarp = blockIdx.x * 8 + (threadIdx.x >> 5);
    int nwarp = gridDim.x * 8;

    for (int qi = gwarp; qi < nfb; qi += nwarp) {
        int slot = g_fb[qi];
        float2 q = g_pts[slot];
        int orig = g_sid[slot];
        float qx = q.x, qy = q.y;

        float best[KNN];
#pragma unroll
        for (int t = 0; t < KNN; ++t) best[t] = FLT_MAX;

#pragma unroll 4
        for (int j = lane; j < NPTS; j += 32) {
            float2 pt = g_pts[j];
            float dx = pt.x - qx;
            float dy = pt.y - qy;
            float d2 = fmaf(dx, dx, dy * dy);
            if (d2 < best[6]) { INSERT7(best, d2); }
        }

        // warp merge: 7 rounds of argmin over each lane's sorted head
        float res[KNN];
#pragma unroll
        for (int t = 0; t < KNN; ++t) {
            float m = best[0];
            int ml = lane;
#pragma unroll
            for (int off = 16; off > 0; off >>= 1) {
                float ov = __shfl_xor_sync(0xffffffffu, m, off);
                int   ol = __shfl_xor_sync(0xffffffffu, ml, off);
                if (ov < m || (ov == m && ol < ml)) { m = ov; ml = ol; }
            }
            res[t] = m;
            if (lane == ml) {
                best[0] = best[1]; best[1] = best[2]; best[2] = best[3];
                best[3] = best[4]; best[4] = best[5]; best[5] = best[6];
                best[6] = FLT_MAX;
            }
        }

        if (lane == 0) {
            float sum = 0.f;
#pragma unroll
            for (int t = 1; t < KNN; ++t)
                sum += sqrtf(fmaxf(res[t], 1e-12f));
            g_mean[orig] = sum * (1.f / (float)(KNN - 1));
        }
    }
}

// ---------------------------------------------------------------------------
// Build stacked activations A[row] = [ silu(x@W1+b1) | silu(m@Wd1+bd1) ]
// ---------------------------------------------------------------------------
__global__ void __launch_bounds__(KTOT) build_A(const float2* __restrict__ coords,
                                                const float* __restrict__ W1,
                                                const float* __restrict__ b1,
                                                const float* __restrict__ Wd1,
                                                const float* __restrict__ bd1) {
    int row = blockIdx.x;
    int k   = threadIdx.x;
    float z;
    if (k < HID) {
        float2 q = coords[row];
        z = fmaf(q.x, W1[k], fmaf(q.y, W1[HID + k], b1[k]));
    } else {
        int   kd = k - HID;
        float m  = g_mean[row];
        z = fmaf(m, Wd1[kd], bd1[kd]);
    }
    float sil = z / (1.f + __expf(-z));
    g_A[row * KTOT + k] = sil;
}

// ---------------------------------------------------------------------------
// out = A @ [W2; Wd2] + (b2 + bd2)
// M=16384, N=256, K=384. BM=128, BN=64, BK=32, 128 threads, 8x8 per thread.
// Inner product uses Blackwell packed fp32: fma.rn.f32x2 (SASS FFMA2) with
// each 64-bit accumulator holding the (n, n+1) output pair -> fma-pipe work
// halves vs scalar FFMA. Exact fp32 math, bit-compatible accumulation order.
// ---------------------------------------------------------------------------
__device__ __forceinline__ unsigned long long bcast2(float v) {
    unsigned long long r;
    asm("mov.b64 %0, {%1, %1};" : "=l"(r) : "f"(v));
    return r;
}
#define FMA_F32X2(d, a, b, c) \
    asm("fma.rn.f32x2 %0, %1, %2, %3;" : "=l"(d) : "l"(a), "l"(b), "l"(c))

__global__ void __launch_bounds__(128, 3) gemm_pass(const float* __restrict__ W2,
                                                    const float* __restrict__ b2,
                                                    const float* __restrict__ Wd2,
                                                    const float* __restrict__ bd2,
                                                    float* __restrict__ out) {
    __shared__ float As[128][33];
    __shared__ float Bs[32][64];

    int bn  = blockIdx.x;
    int bm  = blockIdx.y;
    int tid = threadIdx.x;

    int m0 = (tid >> 3) * 8;
    int n0 = (tid & 7) * 8;

    int rowBase = bm * 128;
    int nBase   = bn * 64;

    int am = tid >> 3;
    int ak = (tid & 7) * 4;
    int bk  = tid >> 4;
    int bn4 = (tid & 15) * 4;

    unsigned long long acc2[8][4];
#pragma unroll
    for (int i = 0; i < 8; ++i)
#pragma unroll
        for (int j = 0; j < 4; ++j) acc2[i][j] = 0ull;

    for (int kt = 0; kt < KTOT; kt += 32) {
#pragma unroll
        for (int i = 0; i < 8; ++i) {
            int m = am + i * 16;
            float4 v = *(const float4*)&g_A[(rowBase + m) * KTOT + kt + ak];
            As[m][ak + 0] = v.x;
            As[m][ak + 1] = v.y;
            As[m][ak + 2] = v.z;
            As[m][ak + 3] = v.w;
        }
#pragma unroll
        for (int i = 0; i < 4; ++i) {
            int kk    = bk + i * 8;
            int kglob = kt + kk;
            const float* src = (kglob < HID)
                                   ? &W2[kglob * HID + nBase + bn4]
                                   : &Wd2[(kglob - HID) * HID + nBase + bn4];
            *(float4*)&Bs[kk][bn4] = *(const float4*)src;
        }
        __syncthreads();

#pragma unroll
        for (int kk = 0; kk < 32; ++kk) {
            unsigned long long bb[4];
            const unsigned long long* bp =
                (const unsigned long long*)&Bs[kk][n0];
#pragma unroll
            for (int j = 0; j < 4; ++j) bb[j] = bp[j];
#pragma unroll
            for (int i = 0; i < 8; ++i) {
                unsigned long long aa = bcast2(As[m0 + i][kk]);
#pragma unroll
                for (int j = 0; j < 4; ++j)
                    FMA_F32X2(acc2[i][j], aa, bb[j], acc2[i][j]);
            }
        }
        __syncthreads();
    }

#pragma unroll
    for (int i = 0; i < 8; ++i) {
        int row = rowBase + m0 + i;
#pragma unroll
        for (int j4 = 0; j4 < 2; ++j4) {
            int n = nBase + n0 + j4 * 4;
            float lo0, hi0, lo1, hi1;
            asm("mov.b64 {%0, %1}, %2;" : "=f"(lo0), "=f"(hi0) : "l"(acc2[i][j4 * 2 + 0]));
            asm("mov.b64 {%0, %1}, %2;" : "=f"(lo1), "=f"(hi1) : "l"(acc2[i][j4 * 2 + 1]));
            float4 o;
            o.x = lo0 + b2[n + 0] + bd2[n + 0];
            o.y = hi0 + b2[n + 1] + bd2[n + 1];
            o.z = lo1 + b2[n + 2] + bd2[n + 2];
            o.w = hi1 + b2[n + 3] + bd2[n + 3];
            *(float4*)&out[row * HID + n] = o;
        }
    }
}

// ---------------------------------------------------------------------------
extern "C" void kernel_launch(void* const* d_in, const int* in_sizes, int n_in,
                              void* d_out, int out_size) {
    (void)in_sizes; (void)n_in; (void)out_size;
    const float2* coords = (const float2*)d_in[0];
    const float*  W1  = (const float*)d_in[1];
    const float*  b1  = (const float*)d_in[2];
    const float*  W2  = (const float*)d_in[3];
    const float*  b2  = (const float*)d_in[4];
    const float*  Wd1 = (const float*)d_in[5];
    const float*  bd1 = (const float*)d_in[6];
    const float*  Wd2 = (const float*)d_in[7];
    const float*  bd2 = (const float*)d_in[8];
    float* out = (float*)d_out;

    zero_counts<<<NCELLS / 1024, 1024>>>();
    count_pts<<<NPTS / 1024, 1024>>>(coords);
    scan_counts<<<1, 1024>>>();
    scatter_pts<<<NPTS / 1024, 1024>>>(coords);
    query_knn<<<NPTS / 256, 256>>>();
    fb_knn<<<64, 256>>>();
    build_A<<<NPTS, KTOT>>>(coords, W1, b1, Wd1, bd1);
    gemm_pass<<<dim3(4, 128), 128>>>(W2, b2, Wd2, bd2, out);
}

// round 8
// speedup vs baseline: 2.7176x; 1.0806x over previous
#include <cuda_runtime.h>
#include <math.h>
#include <float.h>

#define NPTS 16384
#define HID  256
#define KTOT 384                 // stacked K = 256 + 128
#define KNN  7                   // k+1 smallest kept per row

// ---- spatial grid ----
#define GRIDW   128
#define NCELLS  (GRIDW * GRIDW)
#define CELL    1.0f
#define INV_CELL 1.0f
#define ORIGINF (-64.0f)

// Scratch (device globals; no allocation allowed)
__device__ int    g_cnt[NCELLS];
__device__ int    g_start[NCELLS + 1];
__device__ int    g_write[NCELLS];
__device__ float2 g_pts[NPTS];       // points in cell-sorted order
__device__ int    g_sid[NPTS];       // original index per sorted slot
__device__ float  g_mean[NPTS];      // mean kNN distance per row
__device__ float  g_A[NPTS * KTOT];  // stacked activations [h | u]

// ---------------------------------------------------------------------------
__device__ __forceinline__ void cell_of(float x, float y, int& cx, int& cy) {
    cx = min(max(__float2int_rd((x - ORIGINF) * INV_CELL), 0), GRIDW - 1);
    cy = min(max(__float2int_rd((y - ORIGINF) * INV_CELL), 0), GRIDW - 1);
}

__global__ void zero_counts() {
    int i = blockIdx.x * 1024 + threadIdx.x;
    if (i < NCELLS) g_cnt[i] = 0;
}

__global__ void count_pts(const float2* __restrict__ coords) {
    int i = blockIdx.x * 1024 + threadIdx.x;
    if (i >= NPTS) return;
    float2 c = coords[i];
    int cx, cy;
    cell_of(c.x, c.y, cx, cy);
    atomicAdd(&g_cnt[cy * GRIDW + cx], 1);
}

// single-block exclusive scan of NCELLS counts (16 cells per thread)
__global__ void __launch_bounds__(1024) scan_counts() {
    __shared__ int ps[1024];
    int t = threadIdx.x;
    int base = t * (NCELLS / 1024);
    int sum = 0;
#pragma unroll
    for (int c = 0; c < NCELLS / 1024; ++c) sum += g_cnt[base + c];
    ps[t] = sum;
    __syncthreads();
    for (int off = 1; off < 1024; off <<= 1) {
        int v = (t >= off) ? ps[t - off] : 0;
        __syncthreads();
        ps[t] += v;
        __syncthreads();
    }
    int run = ps[t] - sum;
#pragma unroll
    for (int c = 0; c < NCELLS / 1024; ++c) {
        int cnt = g_cnt[base + c];
        g_start[base + c] = run;
        g_write[base + c] = run;
        run += cnt;
    }
    if (t == 1023) g_start[NCELLS] = run;
}

__global__ void scatter_pts(const float2* __restrict__ coords) {
    int i = blockIdx.x * 1024 + threadIdx.x;
    if (i >= NPTS) return;
    float2 c = coords[i];
    int cx, cy;
    cell_of(c.x, c.y, cx, cy);
    int pos = atomicAdd(&g_write[cy * GRIDW + cx], 1);
    g_pts[pos] = c;
    g_sid[pos] = i;
}

// ---------------------------------------------------------------------------
#define INSERT7(B, d2)                                            \
    do {                                                          \
        (B)[6] = (d2);                                            \
        float lo, hi;                                             \
        lo = fminf((B)[5], (B)[6]); hi = fmaxf((B)[5], (B)[6]); (B)[5] = lo; (B)[6] = hi; \
        lo = fminf((B)[4], (B)[5]); hi = fmaxf((B)[4], (B)[5]); (B)[4] = lo; (B)[5] = hi; \
        lo = fminf((B)[3], (B)[4]); hi = fmaxf((B)[3], (B)[4]); (B)[3] = lo; (B)[4] = hi; \
        lo = fminf((B)[2], (B)[3]); hi = fmaxf((B)[2], (B)[3]); (B)[2] = lo; (B)[3] = hi; \
        lo = fminf((B)[1], (B)[2]); hi = fmaxf((B)[1], (B)[2]); (B)[1] = lo; (B)[2] = hi; \
        lo = fminf((B)[0], (B)[1]); hi = fmaxf((B)[0], (B)[1]); (B)[0] = lo; (B)[1] = hi; \
    } while (0)

// Warp-cooperative scan of cells [XA..XB] in row CY (row-major cell sort =>
// one contiguous point range). All 32 lanes serve the same query; lane-strided
// loop => coalesced g_pts loads.
#define VISITW(XA, XB, CY)                                        \
    do {                                                          \
        int st = g_start[(CY) * GRIDW + (XA)];                    \
        int en = g_start[(CY) * GRIDW + (XB) + 1];                \
        for (int p = st + lane; p < en; p += 32) {                \
            float2 pt = g_pts[p];                                 \
            float dx = pt.x - qx;                                 \
            float dy = pt.y - qy;                                 \
            float d2 = fmaf(dx, dx, dy * dy);                     \
            if (d2 < best[6]) { INSERT7(best, d2); }              \
        }                                                         \
    } while (0)

// ---------------------------------------------------------------------------
// Exact kNN: one warp per query, expanding Chebyshev rings.
// After scanning rings 0..r, any unscanned point is >= r*CELL away; resolved
// once >=7 retained candidates have d2 < (r*CELL)^2 (warp-wide count).
// ---------------------------------------------------------------------------
__global__ void __launch_bounds__(256) query_knn_warp() {
    int lane = threadIdx.x & 31;
    int qidx = blockIdx.x * 8 + (threadIdx.x >> 5);   // one warp per query
    float2 q = g_pts[qidx];
    int orig = g_sid[qidx];
    float qx = q.x, qy = q.y;

    float best[KNN];
#pragma unroll
    for (int t = 0; t < KNN; ++t) best[t] = FLT_MAX;

    int cx, cy;
    cell_of(qx, qy, cx, cy);

    for (int r = 0; r < 2 * GRIDW; ++r) {
        if (r == 0) {
            VISITW(cx, cx, cy);
        } else {
            int xa = max(cx - r, 0), xb = min(cx + r, GRIDW - 1);
            int y0 = cy - r, y1 = cy + r;
            if (y0 >= 0)    VISITW(xa, xb, y0);
            if (y1 < GRIDW) VISITW(xa, xb, y1);
            int ya = max(y0 + 1, 0), yb = min(y1 - 1, GRIDW - 1);
            int xl = cx - r, xr = cx + r;
            for (int y = ya; y <= yb; ++y) {
                if (xl >= 0)    VISITW(xl, xl, y);
                if (xr < GRIDW) VISITW(xr, xr, y);
            }
        }
        // resolved iff >=7 candidates strictly inside radius r*CELL
        float bnd2 = ((float)r * CELL) * ((float)r * CELL);
        int cnt = 0;
#pragma unroll
        for (int t = 0; t < KNN; ++t) cnt += (best[t] < bnd2) ? 1 : 0;
        cnt = __reduce_add_sync(0xffffffffu, cnt);
        if (cnt >= KNN) break;
    }

    // warp merge: 7 rounds. d2 >= 0 => float bits order-isomorphic to uint,
    // so one redux.min per round; ballot picks a single pop leader (exact
    // multiset semantics even with duplicate values).
    float res[KNN];
#pragma unroll
    for (int t = 0; t < KNN; ++t) {
        unsigned mbits = __reduce_min_sync(0xffffffffu, __float_as_uint(best[0]));
        res[t] = __uint_as_float(mbits);
        unsigned who = __ballot_sync(0xffffffffu, __float_as_uint(best[0]) == mbits);
        int leader = __ffs(who) - 1;
        if (lane == leader) {
            best[0] = best[1]; best[1] = best[2]; best[2] = best[3];
            best[3] = best[4]; best[4] = best[5]; best[5] = best[6];
            best[6] = FLT_MAX;
        }
    }

    if (lane == 0) {
        float sum = 0.f;
#pragma unroll
        for (int t = 1; t < KNN; ++t)
            sum += sqrtf(fmaxf(res[t], 1e-12f));
        g_mean[orig] = sum * (1.f / (float)(KNN - 1));
    }
}

// ---------------------------------------------------------------------------
// Build stacked activations A[row] = [ silu(x@W1+b1) | silu(m@Wd1+bd1) ]
// ---------------------------------------------------------------------------
__global__ void __launch_bounds__(KTOT) build_A(const float2* __restrict__ coords,
                                                const float* __restrict__ W1,
                                                const float* __restrict__ b1,
                                                const float* __restrict__ Wd1,
                                                const float* __restrict__ bd1) {
    int row = blockIdx.x;
    int k   = threadIdx.x;
    float z;
    if (k < HID) {
        float2 q = coords[row];
        z = fmaf(q.x, W1[k], fmaf(q.y, W1[HID + k], b1[k]));
    } else {
        int   kd = k - HID;
        float m  = g_mean[row];
        z = fmaf(m, Wd1[kd], bd1[kd]);
    }
    float sil = z / (1.f + __expf(-z));
    g_A[row * KTOT + k] = sil;
}

// ---------------------------------------------------------------------------
// out = A @ [W2; Wd2] + (b2 + bd2)
// M=16384, N=256, K=384. BM=128, BN=64, BK=32, 128 threads, 8x8 per thread.
// Inner product uses Blackwell packed fp32 (fma.rn.f32x2 / SASS FFMA2).
// ---------------------------------------------------------------------------
__device__ __forceinline__ unsigned long long bcast2(float v) {
    unsigned long long r;
    asm("mov.b64 %0, {%1, %1};" : "=l"(r) : "f"(v));
    return r;
}
#define FMA_F32X2(d, a, b, c) \
    asm("fma.rn.f32x2 %0, %1, %2, %3;" : "=l"(d) : "l"(a), "l"(b), "l"(c))

__global__ void __launch_bounds__(128, 3) gemm_pass(const float* __restrict__ W2,
                                                    const float* __restrict__ b2,
                                                    const float* __restrict__ Wd2,
                                                    const float* __restrict__ bd2,
                                                    float* __restrict__ out) {
    __shared__ float As[128][33];
    __shared__ float Bs[32][64];

    int bn  = blockIdx.x;
    int bm  = blockIdx.y;
    int tid = threadIdx.x;

    int m0 = (tid >> 3) * 8;
    int n0 = (tid & 7) * 8;

    int rowBase = bm * 128;
    int nBase   = bn * 64;

    int am = tid >> 3;
    int ak = (tid & 7) * 4;
    int bk  = tid >> 4;
    int bn4 = (tid & 15) * 4;

    unsigned long long acc2[8][4];
#pragma unroll
    for (int i = 0; i < 8; ++i)
#pragma unroll
        for (int j = 0; j < 4; ++j) acc2[i][j] = 0ull;

    for (int kt = 0; kt < KTOT; kt += 32) {
#pragma unroll
        for (int i = 0; i < 8; ++i) {
            int m = am + i * 16;
            float4 v = *(const float4*)&g_A[(rowBase + m) * KTOT + kt + ak];
            As[m][ak + 0] = v.x;
            As[m][ak + 1] = v.y;
            As[m][ak + 2] = v.z;
            As[m][ak + 3] = v.w;
        }
#pragma unroll
        for (int i = 0; i < 4; ++i) {
            int kk    = bk + i * 8;
            int kglob = kt + kk;
            const float* src = (kglob < HID)
                                   ? &W2[kglob * HID + nBase + bn4]
                                   : &Wd2[(kglob - HID) * HID + nBase + bn4];
            *(float4*)&Bs[kk][bn4] = *(const float4*)src;
        }
        __syncthreads();

#pragma unroll
        for (int kk = 0; kk < 32; ++kk) {
            unsigned long long bb[4];
            const unsigned long long* bp =
                (const unsigned long long*)&Bs[kk][n0];
#pragma unroll
            for (int j = 0; j < 4; ++j) bb[j] = bp[j];
#pragma unroll
            for (int i = 0; i < 8; ++i) {
                unsigned long long aa = bcast2(As[m0 + i][kk]);
#pragma unroll
                for (int j = 0; j < 4; ++j)
                    FMA_F32X2(acc2[i][j], aa, bb[j], acc2[i][j]);
            }
        }
        __syncthreads();
    }

#pragma unroll
    for (int i = 0; i < 8; ++i) {
        int row = rowBase + m0 + i;
#pragma unroll
        for (int j4 = 0; j4 < 2; ++j4) {
            int n = nBase + n0 + j4 * 4;
            float lo0, hi0, lo1, hi1;
            asm("mov.b64 {%0, %1}, %2;" : "=f"(lo0), "=f"(hi0) : "l"(acc2[i][j4 * 2 + 0]));
            asm("mov.b64 {%0, %1}, %2;" : "=f"(lo1), "=f"(hi1) : "l"(acc2[i][j4 * 2 + 1]));
            float4 o;
            o.x = lo0 + b2[n + 0] + bd2[n + 0];
            o.y = hi0 + b2[n + 1] + bd2[n + 1];
            o.z = lo1 + b2[n + 2] + bd2[n + 2];
            o.w = hi1 + b2[n + 3] + bd2[n + 3];
            *(float4*)&out[row * HID + n] = o;
        }
    }
}

// ---------------------------------------------------------------------------
extern "C" void kernel_launch(void* const* d_in, const int* in_sizes, int n_in,
                              void* d_out, int out_size) {
    (void)in_sizes; (void)n_in; (void)out_size;
    const float2* coords = (const float2*)d_in[0];
    const float*  W1  = (const float*)d_in[1];
    const float*  b1  = (const float*)d_in[2];
    const float*  W2  = (const float*)d_in[3];
    const float*  b2  = (const float*)d_in[4];
    const float*  Wd1 = (const float*)d_in[5];
    const float*  bd1 = (const float*)d_in[6];
    const float*  Wd2 = (const float*)d_in[7];
    const float*  bd2 = (const float*)d_in[8];
    float* out = (float*)d_out;

    zero_counts<<<NCELLS / 1024, 1024>>>();
    count_pts<<<NPTS / 1024, 1024>>>(coords);
    scan_counts<<<1, 1024>>>();
    scatter_pts<<<NPTS / 1024, 1024>>>(coords);
    query_knn_warp<<<NPTS / 8, 256>>>();   // one warp per query
    build_A<<<NPTS, KTOT>>>(coords, W1, b1, Wd1, bd1);
    gemm_pass<<<dim3(4, 128), 128>>>(W2, b2, Wd2, bd2, out);
}

// round 15
// speedup vs baseline: 3.4104x; 1.2549x over previous
#include <cuda_runtime.h>
#include <cuda_bf16.h>
#include <cstdint>
#include <math.h>
#include <float.h>

#define NPTS 16384
#define HID  256
#define KTOT 384                 // stacked K = 256 + 128
#define KNN  7                   // k+1 smallest kept per row

// ---- spatial grid ----
#define GRIDW   128
#define NCELLS  (GRIDW * GRIDW)
#define CELL    1.0f
#define INV_CELL 1.0f
#define ORIGINF (-64.0f)

// Scratch (device globals; no allocation allowed)
__device__ int    g_cnt[NCELLS];
__device__ int    g_start[NCELLS + 1];
__device__ int    g_write[NCELLS];
__device__ float2 g_pts[NPTS];       // points in cell-sorted order
__device__ int    g_sid[NPTS];       // original index per sorted slot
__device__ float  g_mean[NPTS];      // mean kNN distance per row
// bf16 hi/lo split operand images: A [row][k] row-major, B [n][k] (k-contig)
__device__ __nv_bfloat16 g_Ahi[NPTS * KTOT];
__device__ __nv_bfloat16 g_Alo[NPTS * KTOT];
__device__ __nv_bfloat16 g_Bhi[HID * KTOT];
__device__ __nv_bfloat16 g_Blo[HID * KTOT];

// ---------------------------------------------------------------------------
__device__ __forceinline__ void cell_of(float x, float y, int& cx, int& cy) {
    cx = min(max(__float2int_rd((x - ORIGINF) * INV_CELL), 0), GRIDW - 1);
    cy = min(max(__float2int_rd((y - ORIGINF) * INV_CELL), 0), GRIDW - 1);
}

__global__ void zero_counts() {
    int i = blockIdx.x * 1024 + threadIdx.x;
    if (i < NCELLS) g_cnt[i] = 0;
}

__global__ void count_pts(const float2* __restrict__ coords) {
    int i = blockIdx.x * 1024 + threadIdx.x;
    if (i >= NPTS) return;
    float2 c = coords[i];
    int cx, cy;
    cell_of(c.x, c.y, cx, cy);
    atomicAdd(&g_cnt[cy * GRIDW + cx], 1);
}

__global__ void __launch_bounds__(1024) scan_counts() {
    __shared__ int ps[1024];
    int t = threadIdx.x;
    int base = t * (NCELLS / 1024);
    int sum = 0;
#pragma unroll
    for (int c = 0; c < NCELLS / 1024; ++c) sum += g_cnt[base + c];
    ps[t] = sum;
    __syncthreads();
    for (int off = 1; off < 1024; off <<= 1) {
        int v = (t >= off) ? ps[t - off] : 0;
        __syncthreads();
        ps[t] += v;
        __syncthreads();
    }
    int run = ps[t] - sum;
#pragma unroll
    for (int c = 0; c < NCELLS / 1024; ++c) {
        int cnt = g_cnt[base + c];
        g_start[base + c] = run;
        g_write[base + c] = run;
        run += cnt;
    }
    if (t == 1023) g_start[NCELLS] = run;
}

__global__ void scatter_pts(const float2* __restrict__ coords) {
    int i = blockIdx.x * 1024 + threadIdx.x;
    if (i >= NPTS) return;
    float2 c = coords[i];
    int cx, cy;
    cell_of(c.x, c.y, cx, cy);
    int pos = atomicAdd(&g_write[cy * GRIDW + cx], 1);
    g_pts[pos] = c;
    g_sid[pos] = i;
}

// ---------------------------------------------------------------------------
#define INSERT7(B, d2)                                            \
    do {                                                          \
        (B)[6] = (d2);                                            \
        float lo, hi;                                             \
        lo = fminf((B)[5], (B)[6]); hi = fmaxf((B)[5], (B)[6]); (B)[5] = lo; (B)[6] = hi; \
        lo = fminf((B)[4], (B)[5]); hi = fmaxf((B)[4], (B)[5]); (B)[4] = lo; (B)[5] = hi; \
        lo = fminf((B)[3], (B)[4]); hi = fmaxf((B)[3], (B)[4]); (B)[3] = lo; (B)[4] = hi; \
        lo = fminf((B)[2], (B)[3]); hi = fmaxf((B)[2], (B)[3]); (B)[2] = lo; (B)[3] = hi; \
        lo = fminf((B)[1], (B)[2]); hi = fmaxf((B)[1], (B)[2]); (B)[1] = lo; (B)[2] = hi; \
        lo = fminf((B)[0], (B)[1]); hi = fmaxf((B)[0], (B)[1]); (B)[0] = lo; (B)[1] = hi; \
    } while (0)

#define VISITW(XA, XB, CY)                                        \
    do {                                                          \
        int st = g_start[(CY) * GRIDW + (XA)];                    \
        int en = g_start[(CY) * GRIDW + (XB) + 1];                \
        for (int p = st + lane; p < en; p += 32) {                \
            float2 pt = g_pts[p];                                 \
            float dx = pt.x - qx;                                 \
            float dy = pt.y - qy;                                 \
            float d2 = fmaf(dx, dx, dy * dy);                     \
            if (d2 < best[6]) { INSERT7(best, d2); }              \
        }                                                         \
    } while (0)

__global__ void __launch_bounds__(256) query_knn_warp() {
    int lane = threadIdx.x & 31;
    int qidx = blockIdx.x * 8 + (threadIdx.x >> 5);
    float2 q = g_pts[qidx];
    int orig = g_sid[qidx];
    float qx = q.x, qy = q.y;

    float best[KNN];
#pragma unroll
    for (int t = 0; t < KNN; ++t) best[t] = FLT_MAX;

    int cx, cy;
    cell_of(qx, qy, cx, cy);

    for (int r = 0; r < 2 * GRIDW; ++r) {
        if (r == 0) {
            VISITW(cx, cx, cy);
        } else {
            int xa = max(cx - r, 0), xb = min(cx + r, GRIDW - 1);
            int y0 = cy - r, y1 = cy + r;
            if (y0 >= 0)    VISITW(xa, xb, y0);
            if (y1 < GRIDW) VISITW(xa, xb, y1);
            int ya = max(y0 + 1, 0), yb = min(y1 - 1, GRIDW - 1);
            int xl = cx - r, xr = cx + r;
            for (int y = ya; y <= yb; ++y) {
                if (xl >= 0)    VISITW(xl, xl, y);
                if (xr < GRIDW) VISITW(xr, xr, y);
            }
        }
        float bnd2 = ((float)r * CELL) * ((float)r * CELL);
        int cnt = 0;
#pragma unroll
        for (int t = 0; t < KNN; ++t) cnt += (best[t] < bnd2) ? 1 : 0;
        cnt = __reduce_add_sync(0xffffffffu, cnt);
        if (cnt >= KNN) break;
    }

    float res[KNN];
#pragma unroll
    for (int t = 0; t < KNN; ++t) {
        unsigned mbits = __reduce_min_sync(0xffffffffu, __float_as_uint(best[0]));
        res[t] = __uint_as_float(mbits);
        unsigned who = __ballot_sync(0xffffffffu, __float_as_uint(best[0]) == mbits);
        int leader = __ffs(who) - 1;
        if (lane == leader) {
            best[0] = best[1]; best[1] = best[2]; best[2] = best[3];
            best[3] = best[4]; best[4] = best[5]; best[5] = best[6];
            best[6] = FLT_MAX;
        }
    }

    if (lane == 0) {
        float sum = 0.f;
#pragma unroll
        for (int t = 1; t < KNN; ++t)
            sum += sqrtf(fmaxf(res[t], 1e-12f));
        g_mean[orig] = sum * (1.f / (float)(KNN - 1));
    }
}

// ---------------------------------------------------------------------------
// Weight prep: split stacked [W2; Wd2] (K=384, N=256) into bf16 hi/lo,
// transposed to [n][k] (k contiguous, ready for col-major B fragments).
// ---------------------------------------------------------------------------
__global__ void __launch_bounds__(256) conv_B(const float* __restrict__ W2,
                                              const float* __restrict__ Wd2) {
    int k = blockIdx.x;      // 0..383
    int n = threadIdx.x;     // 0..255
    float w = (k < HID) ? W2[k * HID + n] : Wd2[(k - HID) * HID + n];
    __nv_bfloat16 hi = __float2bfloat16(w);
    float lof = w - __bfloat162float(hi);
    __nv_bfloat16 lo = __float2bfloat16(lof);
    g_Bhi[n * KTOT + k] = hi;
    g_Blo[n * KTOT + k] = lo;
}

// ---------------------------------------------------------------------------
// Build stacked activations, split to bf16 hi/lo, row-major [row][k].
// ---------------------------------------------------------------------------
__global__ void __launch_bounds__(KTOT) build_A(const float2* __restrict__ coords,
                                                const float* __restrict__ W1,
                                                const float* __restrict__ b1,
                                                const float* __restrict__ Wd1,
                                                const float* __restrict__ bd1) {
    int row = blockIdx.x;
    int k   = threadIdx.x;
    float z;
    if (k < HID) {
        float2 q = coords[row];
        z = fmaf(q.x, W1[k], fmaf(q.y, W1[HID + k], b1[k]));
    } else {
        int   kd = k - HID;
        float m  = g_mean[row];
        z = fmaf(m, Wd1[kd], bd1[kd]);
    }
    float sil = z / (1.f + __expf(-z));
    __nv_bfloat16 hi = __float2bfloat16(sil);
    float lof = sil - __bfloat162float(hi);
    __nv_bfloat16 lo = __float2bfloat16(lof);
    g_Ahi[row * KTOT + k] = hi;
    g_Alo[row * KTOT + k] = lo;
}

// ---------------------------------------------------------------------------
// mma.sync bf16 GEMM (HMMA path; compiles for plain sm_103):
// out = Ahi*Bhi + Ahi*Blo + Alo*Bhi + (b2+bd2), fp32 accumulation.
// Block 256 thr = 8 warps (4 M x 2 N), tile 128x128, BK=32, warp tile 32x64.
// SMEM stride 40 bf16 -> conflict-free 32-bit fragment LDS for both A and B.
// ---------------------------------------------------------------------------
#define SA 40   // smem row stride in bf16

__device__ __forceinline__ void mma16816(float* c, const uint32_t* a,
                                         const uint32_t* b) {
    asm volatile(
        "mma.sync.aligned.m16n8k16.row.col.f32.bf16.bf16.f32 "
        "{%0,%1,%2,%3}, {%4,%5,%6,%7}, {%8,%9}, {%0,%1,%2,%3};"
        : "+f"(c[0]), "+f"(c[1]), "+f"(c[2]), "+f"(c[3])
        : "r"(a[0]), "r"(a[1]), "r"(a[2]), "r"(a[3]), "r"(b[0]), "r"(b[1]));
}

__global__ void __launch_bounds__(256, 2) gemm_mma(const float* __restrict__ b2,
                                                   const float* __restrict__ bd2,
                                                   float* __restrict__ out) {
    __shared__ __nv_bfloat16 Ash[128 * SA];
    __shared__ __nv_bfloat16 Asl[128 * SA];
    __shared__ __nv_bfloat16 Bsh[128 * SA];
    __shared__ __nv_bfloat16 Bsl[128 * SA];

    int tid  = threadIdx.x;
    int lane = tid & 31;
    int wid  = tid >> 5;        // 0..7
    int wm   = wid & 3;         // 0..3 -> 32-row band
    int wn   = wid >> 2;        // 0..1 -> 64-col band
    int g    = lane >> 2;       // 0..7
    int tg   = lane & 3;        // 0..3

    int rowBase = blockIdx.y * 128;
    int nBase   = blockIdx.x * 128;

    // global<->smem copy mapping: per tile array, each thread moves 16 bf16
    // (two uint4) covering k offsets [lhalf, lhalf+16) of the 32-wide chunk.
    int lrow  = tid >> 1;           // 0..127
    int lhalf = (tid & 1) * 16;     // bf16 k-offset: 0 or 16

    float acc[2][8][4];
#pragma unroll
    for (int mi = 0; mi < 2; ++mi)
#pragma unroll
        for (int ni = 0; ni < 8; ++ni)
#pragma unroll
            for (int c = 0; c < 4; ++c) acc[mi][ni][c] = 0.f;

    for (int kt = 0; kt < KTOT; kt += 32) {
        // ---- load tiles: A rows rowBase..+127, B rows (n) nBase..+127 ----
        {
            size_t gA = (size_t)(rowBase + lrow) * KTOT + kt + lhalf;
            size_t gB = (size_t)(nBase + lrow) * KTOT + kt + lhalf;
            int s = lrow * SA + lhalf;
            *(uint4*)&Ash[s]     = *(const uint4*)&g_Ahi[gA];
            *(uint4*)&Ash[s + 8] = *(const uint4*)&g_Ahi[gA + 8];
            *(uint4*)&Asl[s]     = *(const uint4*)&g_Alo[gA];
            *(uint4*)&Asl[s + 8] = *(const uint4*)&g_Alo[gA + 8];
            *(uint4*)&Bsh[s]     = *(const uint4*)&g_Bhi[gB];
            *(uint4*)&Bsh[s + 8] = *(const uint4*)&g_Bhi[gB + 8];
            *(uint4*)&Bsl[s]     = *(const uint4*)&g_Blo[gB];
            *(uint4*)&Bsl[s + 8] = *(const uint4*)&g_Blo[gB + 8];
        }
        __syncthreads();

#pragma unroll
        for (int ko = 0; ko < 32; ko += 16) {
            // A fragments for both 16-row subtiles (hi and lo)
            uint32_t ahi[2][4], alo[2][4];
#pragma unroll
            for (int mi = 0; mi < 2; ++mi) {
                int r0 = (wm * 32 + mi * 16 + g) * SA + 2 * tg + ko;
                int r1 = r0 + 8 * SA;
                ahi[mi][0] = *(const uint32_t*)&Ash[r0];
                ahi[mi][1] = *(const uint32_t*)&Ash[r1];
                ahi[mi][2] = *(const uint32_t*)&Ash[r0 + 8];
                ahi[mi][3] = *(const uint32_t*)&Ash[r1 + 8];
                alo[mi][0] = *(const uint32_t*)&Asl[r0];
                alo[mi][1] = *(const uint32_t*)&Asl[r1];
                alo[mi][2] = *(const uint32_t*)&Asl[r0 + 8];
                alo[mi][3] = *(const uint32_t*)&Asl[r1 + 8];
            }
#pragma unroll
            for (int ni = 0; ni < 8; ++ni) {
                int nb = (wn * 64 + ni * 8 + g) * SA + 2 * tg + ko;
                uint32_t bhi[2], blo[2];
                bhi[0] = *(const uint32_t*)&Bsh[nb];
                bhi[1] = *(const uint32_t*)&Bsh[nb + 8];
                blo[0] = *(const uint32_t*)&Bsl[nb];
                blo[1] = *(const uint32_t*)&Bsl[nb + 8];
#pragma unroll
                for (int mi = 0; mi < 2; ++mi) {
                    mma16816(acc[mi][ni], ahi[mi], bhi);
                    mma16816(acc[mi][ni], ahi[mi], blo);
                    mma16816(acc[mi][ni], alo[mi], bhi);
                }
            }
        }
        __syncthreads();
    }

    // epilogue: c0,c1 -> (row, 2tg..2tg+1), c2,c3 -> (row+8, same cols)
#pragma unroll
    for (int mi = 0; mi < 2; ++mi) {
#pragma unroll
        for (int ni = 0; ni < 8; ++ni) {
            int row = rowBase + wm * 32 + mi * 16 + g;
            int col = nBase + wn * 64 + ni * 8 + 2 * tg;
            float bias0 = b2[col] + bd2[col];
            float bias1 = b2[col + 1] + bd2[col + 1];
            float2 o0 = make_float2(acc[mi][ni][0] + bias0,
                                    acc[mi][ni][1] + bias1);
            float2 o1 = make_float2(acc[mi][ni][2] + bias0,
                                    acc[mi][ni][3] + bias1);
            *(float2*)&out[(size_t)row * HID + col]       = o0;
            *(float2*)&out[(size_t)(row + 8) * HID + col] = o1;
        }
    }
}

// ---------------------------------------------------------------------------
extern "C" void kernel_launch(void* const* d_in, const int* in_sizes, int n_in,
                              void* d_out, int out_size) {
    (void)in_sizes; (void)n_in; (void)out_size;
    const float2* coords = (const float2*)d_in[0];
    const float*  W1  = (const float*)d_in[1];
    const float*  b1  = (const float*)d_in[2];
    const float*  W2  = (const float*)d_in[3];
    const float*  b2  = (const float*)d_in[4];
    const float*  Wd1 = (const float*)d_in[5];
    const float*  bd1 = (const float*)d_in[6];
    const float*  Wd2 = (const float*)d_in[7];
    const float*  bd2 = (const float*)d_in[8];
    float* out = (float*)d_out;

    zero_counts<<<NCELLS / 1024, 1024>>>();
    count_pts<<<NPTS / 1024, 1024>>>(coords);
    scan_counts<<<1, 1024>>>();
    scatter_pts<<<NPTS / 1024, 1024>>>(coords);
    query_knn_warp<<<NPTS / 8, 256>>>();
    conv_B<<<KTOT, 256>>>(W2, Wd2);
    build_A<<<NPTS, KTOT>>>(coords, W1, b1, Wd1, bd1);
    gemm_mma<<<dim3(2, 128), 256>>>(b2, bd2, out);
}

// round 16
// speedup vs baseline: 3.6844x; 1.0803x over previous
#include <cuda_runtime.h>
#include <cuda_bf16.h>
#include <cstdint>
#include <math.h>
#include <float.h>

#define NPTS 16384
#define HID  256
#define KTOT 384                 // stacked K = 256 + 128
#define KNN  7                   // k+1 smallest kept per row

// ---- spatial grid ----
#define GRIDW   128
#define NCELLS  (GRIDW * GRIDW)
#define CELL    1.0f
#define INV_CELL 1.0f
#define ORIGINF (-64.0f)

// Scratch (device globals; no allocation allowed)
__device__ int    g_cnt[NCELLS];     // zero at load; re-zeroed by scatter_pts
__device__ int    g_start[NCELLS + 1];
__device__ int    g_write[NCELLS];
__device__ float2 g_pts[NPTS];       // points in cell-sorted order
__device__ int    g_sid[NPTS];       // original index per sorted slot
// bf16 hi/lo split operand images: A [row][k] row-major, B [n][k] (k-contig)
__device__ __nv_bfloat16 g_Ahi[NPTS * KTOT];
__device__ __nv_bfloat16 g_Alo[NPTS * KTOT];
__device__ __nv_bfloat16 g_Bhi[HID * KTOT];
__device__ __nv_bfloat16 g_Blo[HID * KTOT];

// ---------------------------------------------------------------------------
__device__ __forceinline__ void cell_of(float x, float y, int& cx, int& cy) {
    cx = min(max(__float2int_rd((x - ORIGINF) * INV_CELL), 0), GRIDW - 1);
    cy = min(max(__float2int_rd((y - ORIGINF) * INV_CELL), 0), GRIDW - 1);
}

// ---------------------------------------------------------------------------
// Fused: blocks 0..15 count points into cells; blocks 16..111 split/transpose
// the stacked weight matrix [W2; Wd2] into bf16 hi/lo images.
// ---------------------------------------------------------------------------
__global__ void __launch_bounds__(1024) count_and_convB(
        const float2* __restrict__ coords,
        const float* __restrict__ W2, const float* __restrict__ Wd2) {
    if (blockIdx.x < 16) {
        int i = blockIdx.x * 1024 + threadIdx.x;
        float2 c = coords[i];
        int cx, cy;
        cell_of(c.x, c.y, cx, cy);
        atomicAdd(&g_cnt[cy * GRIDW + cx], 1);
    } else {
        int idx = (blockIdx.x - 16) * 1024 + threadIdx.x;  // 0..98303
        int k = idx >> 8;        // 0..383
        int n = idx & 255;       // 0..255
        float w = (k < HID) ? W2[k * HID + n] : Wd2[(k - HID) * HID + n];
        __nv_bfloat16 hi = __float2bfloat16(w);
        float lof = w - __bfloat162float(hi);
        g_Bhi[n * KTOT + k] = hi;
        g_Blo[n * KTOT + k] = __float2bfloat16(lof);
    }
}

__global__ void __launch_bounds__(1024) scan_counts() {
    __shared__ int ps[1024];
    int t = threadIdx.x;
    int base = t * (NCELLS / 1024);
    int sum = 0;
#pragma unroll
    for (int c = 0; c < NCELLS / 1024; ++c) sum += g_cnt[base + c];
    ps[t] = sum;
    __syncthreads();
    for (int off = 1; off < 1024; off <<= 1) {
        int v = (t >= off) ? ps[t - off] : 0;
        __syncthreads();
        ps[t] += v;
        __syncthreads();
    }
    int run = ps[t] - sum;
#pragma unroll
    for (int c = 0; c < NCELLS / 1024; ++c) {
        int cnt = g_cnt[base + c];
        g_start[base + c] = run;
        g_write[base + c] = run;
        run += cnt;
    }
    if (t == 1023) g_start[NCELLS] = run;
}

// scatter + re-zero g_cnt for the next graph replay (g_cnt is dead after scan)
__global__ void scatter_pts(const float2* __restrict__ coords) {
    int i = blockIdx.x * 1024 + threadIdx.x;
    if (i >= NPTS) return;
    g_cnt[i] = 0;                      // NCELLS == NPTS
    float2 c = coords[i];
    int cx, cy;
    cell_of(c.x, c.y, cx, cy);
    int pos = atomicAdd(&g_write[cy * GRIDW + cx], 1);
    g_pts[pos] = c;
    g_sid[pos] = i;
}

// ---------------------------------------------------------------------------
#define INSERT7(B, d2)                                            \
    do {                                                          \
        (B)[6] = (d2);                                            \
        float lo, hi;                                             \
        lo = fminf((B)[5], (B)[6]); hi = fmaxf((B)[5], (B)[6]); (B)[5] = lo; (B)[6] = hi; \
        lo = fminf((B)[4], (B)[5]); hi = fmaxf((B)[4], (B)[5]); (B)[4] = lo; (B)[5] = hi; \
        lo = fminf((B)[3], (B)[4]); hi = fmaxf((B)[3], (B)[4]); (B)[3] = lo; (B)[4] = hi; \
        lo = fminf((B)[2], (B)[3]); hi = fmaxf((B)[2], (B)[3]); (B)[2] = lo; (B)[3] = hi; \
        lo = fminf((B)[1], (B)[2]); hi = fmaxf((B)[1], (B)[2]); (B)[1] = lo; (B)[2] = hi; \
        lo = fminf((B)[0], (B)[1]); hi = fmaxf((B)[0], (B)[1]); (B)[0] = lo; (B)[1] = hi; \
    } while (0)

#define VISITW(XA, XB, CY)                                        \
    do {                                                          \
        int st = g_start[(CY) * GRIDW + (XA)];                    \
        int en = g_start[(CY) * GRIDW + (XB) + 1];                \
        for (int p = st + lane; p < en; p += 32) {                \
            float2 pt = g_pts[p];                                 \
            float dx = pt.x - qx;                                 \
            float dy = pt.y - qy;                                 \
            float d2 = fmaf(dx, dx, dy * dy);                     \
            if (d2 < best[6]) { INSERT7(best, d2); }              \
        }                                                         \
    } while (0)

// ---------------------------------------------------------------------------
// Fused: one warp per query. Exact kNN by expanding rings, then the same warp
// emits the row's 384 split activations (mean broadcast via shfl).
// ---------------------------------------------------------------------------
__global__ void __launch_bounds__(256) query_and_buildA(
        const float* __restrict__ W1,  const float* __restrict__ b1,
        const float* __restrict__ Wd1, const float* __restrict__ bd1) {
    int lane = threadIdx.x & 31;
    int qidx = blockIdx.x * 8 + (threadIdx.x >> 5);
    float2 q = g_pts[qidx];
    int orig = g_sid[qidx];
    float qx = q.x, qy = q.y;

    float best[KNN];
#pragma unroll
    for (int t = 0; t < KNN; ++t) best[t] = FLT_MAX;

    int cx, cy;
    cell_of(qx, qy, cx, cy);

    for (int r = 0; r < 2 * GRIDW; ++r) {
        if (r == 0) {
            VISITW(cx, cx, cy);
        } else {
            int xa = max(cx - r, 0), xb = min(cx + r, GRIDW - 1);
            int y0 = cy - r, y1 = cy + r;
            if (y0 >= 0)    VISITW(xa, xb, y0);
            if (y1 < GRIDW) VISITW(xa, xb, y1);
            int ya = max(y0 + 1, 0), yb = min(y1 - 1, GRIDW - 1);
            int xl = cx - r, xr = cx + r;
            for (int y = ya; y <= yb; ++y) {
                if (xl >= 0)    VISITW(xl, xl, y);
                if (xr < GRIDW) VISITW(xr, xr, y);
            }
        }
        float bnd2 = ((float)r * CELL) * ((float)r * CELL);
        int cnt = 0;
#pragma unroll
        for (int t = 0; t < KNN; ++t) cnt += (best[t] < bnd2) ? 1 : 0;
        cnt = __reduce_add_sync(0xffffffffu, cnt);
        if (cnt >= KNN) break;
    }

    // warp merge (value multiset -> deterministic): 7 redux.min rounds
    float res[KNN];
#pragma unroll
    for (int t = 0; t < KNN; ++t) {
        unsigned mbits = __reduce_min_sync(0xffffffffu, __float_as_uint(best[0]));
        res[t] = __uint_as_float(mbits);
        unsigned who = __ballot_sync(0xffffffffu, __float_as_uint(best[0]) == mbits);
        int leader = __ffs(who) - 1;
        if (lane == leader) {
            best[0] = best[1]; best[1] = best[2]; best[2] = best[3];
            best[3] = best[4]; best[4] = best[5]; best[5] = best[6];
            best[6] = FLT_MAX;
        }
    }

    float m;
    if (lane == 0) {
        float sum = 0.f;
#pragma unroll
        for (int t = 1; t < KNN; ++t)
            sum += sqrtf(fmaxf(res[t], 1e-12f));
        m = sum * (1.f / (float)(KNN - 1));
    }
    m = __shfl_sync(0xffffffffu, m, 0);

    // emit split activations for this row: lanes stride k (coalesced stores)
    size_t rowBase = (size_t)orig * KTOT;
#pragma unroll
    for (int j = 0; j < KTOT / 32; ++j) {
        int k = j * 32 + lane;
        float z;
        if (k < HID) {
            z = fmaf(qx, W1[k], fmaf(qy, W1[HID + k], b1[k]));
        } else {
            int kd = k - HID;
            z = fmaf(m, Wd1[kd], bd1[kd]);
        }
        float sil = z / (1.f + __expf(-z));
        __nv_bfloat16 hi = __float2bfloat16(sil);
        float lof = sil - __bfloat162float(hi);
        g_Ahi[rowBase + k] = hi;
        g_Alo[rowBase + k] = __float2bfloat16(lof);
    }
}

// ---------------------------------------------------------------------------
// mma.sync bf16 GEMM (HMMA): out = Ahi*Bhi + Ahi*Blo + Alo*Bhi + (b2+bd2).
// Block 256 thr = 8 warps (4 M x 2 N), tile 128x128, BK=32, warp tile 32x64.
// Fragment loads via ldmatrix.x4 (12 LDSM per ko vs 48 LDS). SA=40 stride
// keeps all 8-row ldmatrix phases on distinct banks (20*i mod 32 distinct).
// ---------------------------------------------------------------------------
#define SA 40   // smem row stride in bf16

__device__ __forceinline__ void mma16816(float* c, const uint32_t* a,
                                         const uint32_t* b) {
    asm volatile(
        "mma.sync.aligned.m16n8k16.row.col.f32.bf16.bf16.f32 "
        "{%0,%1,%2,%3}, {%4,%5,%6,%7}, {%8,%9}, {%0,%1,%2,%3};"
        : "+f"(c[0]), "+f"(c[1]), "+f"(c[2]), "+f"(c[3])
        : "r"(a[0]), "r"(a[1]), "r"(a[2]), "r"(a[3]), "r"(b[0]), "r"(b[1]));
}

__device__ __forceinline__ void ldsm4(uint32_t* d, uint32_t addr) {
    asm volatile(
        "ldmatrix.sync.aligned.m8n8.x4.shared.b16 {%0,%1,%2,%3}, [%4];"
        : "=r"(d[0]), "=r"(d[1]), "=r"(d[2]), "=r"(d[3]) : "r"(addr));
}

__global__ void __launch_bounds__(256, 2) gemm_mma(const float* __restrict__ b2,
                                                   const float* __restrict__ bd2,
                                                   float* __restrict__ out) {
    __shared__ __nv_bfloat16 Ash[128 * SA];
    __shared__ __nv_bfloat16 Asl[128 * SA];
    __shared__ __nv_bfloat16 Bsh[128 * SA];
    __shared__ __nv_bfloat16 Bsl[128 * SA];

    int tid  = threadIdx.x;
    int lane = tid & 31;
    int wid  = tid >> 5;        // 0..7
    int wm   = wid & 3;         // 0..3 -> 32-row band
    int wn   = wid >> 2;        // 0..1 -> 64-col band
    int g    = lane >> 2;       // 0..7
    int tg   = lane & 3;        // 0..3

    int rowBase = blockIdx.y * 128;
    int nBase   = blockIdx.x * 128;

    int lrow  = tid >> 1;           // 0..127
    int lhalf = (tid & 1) * 16;     // bf16 k-offset: 0 or 16

    // ldmatrix lane-address components
    int r8  = lane & 7;
    int sel = lane >> 3;            // 0..3
    // A x4: m0=(rows 0-7,k 0-7)->a0, m1=(rows 8-15)->a1, m2=(k+8)->a2, m3->a3
    int aRow = wm * 32 + ((sel & 1) << 3) + r8;     // + mi*16
    int aCol = (sel >> 1) << 3;                     // + ko
    // B x4: m0=(n 0-7,k lo)->b0[ni even], m1=(n 0-7,k hi)->b1[ni even],
    //       m2=(n 8-15,k lo)->b0[ni odd], m3->b1[ni odd]
    int bRow = wn * 64 + ((sel >> 1) << 3) + r8;    // + nip*16
    int bCol = (sel & 1) << 3;                      // + ko

    uint32_t sAsh = (uint32_t)__cvta_generic_to_shared(Ash);
    uint32_t sAsl = (uint32_t)__cvta_generic_to_shared(Asl);
    uint32_t sBsh = (uint32_t)__cvta_generic_to_shared(Bsh);
    uint32_t sBsl = (uint32_t)__cvta_generic_to_shared(Bsl);

    float acc[2][8][4];
#pragma unroll
    for (int mi = 0; mi < 2; ++mi)
#pragma unroll
        for (int ni = 0; ni < 8; ++ni)
#pragma unroll
            for (int c = 0; c < 4; ++c) acc[mi][ni][c] = 0.f;

    for (int kt = 0; kt < KTOT; kt += 32) {
        {
            size_t gA = (size_t)(rowBase + lrow) * KTOT + kt + lhalf;
            size_t gB = (size_t)(nBase + lrow) * KTOT + kt + lhalf;
            int s = lrow * SA + lhalf;
            *(uint4*)&Ash[s]     = *(const uint4*)&g_Ahi[gA];
            *(uint4*)&Ash[s + 8] = *(const uint4*)&g_Ahi[gA + 8];
            *(uint4*)&Asl[s]     = *(const uint4*)&g_Alo[gA];
            *(uint4*)&Asl[s + 8] = *(const uint4*)&g_Alo[gA + 8];
            *(uint4*)&Bsh[s]     = *(const uint4*)&g_Bhi[gB];
            *(uint4*)&Bsh[s + 8] = *(const uint4*)&g_Bhi[gB + 8];
            *(uint4*)&Bsl[s]     = *(const uint4*)&g_Blo[gB];
            *(uint4*)&Bsl[s + 8] = *(const uint4*)&g_Blo[gB + 8];
        }
        __syncthreads();

#pragma unroll
        for (int ko = 0; ko < 32; ko += 16) {
            uint32_t ahi[2][4], alo[2][4];
#pragma unroll
            for (int mi = 0; mi < 2; ++mi) {
                uint32_t aoff = (uint32_t)((aRow + mi * 16) * SA + aCol + ko) * 2u;
                ldsm4(ahi[mi], sAsh + aoff);
                ldsm4(alo[mi], sAsl + aoff);
            }
#pragma unroll
            for (int nip = 0; nip < 4; ++nip) {
                uint32_t boff = (uint32_t)((bRow + nip * 16) * SA + bCol + ko) * 2u;
                uint32_t bh[4], bl[4];
                ldsm4(bh, sBsh + boff);
                ldsm4(bl, sBsl + boff);
#pragma unroll
                for (int sub = 0; sub < 2; ++sub) {
                    int ni = nip * 2 + sub;
#pragma unroll
                    for (int mi = 0; mi < 2; ++mi) {
                        mma16816(acc[mi][ni], ahi[mi], &bh[sub * 2]);
                        mma16816(acc[mi][ni], ahi[mi], &bl[sub * 2]);
                        mma16816(acc[mi][ni], alo[mi], &bh[sub * 2]);
                    }
                }
            }
        }
        __syncthreads();
    }

    // epilogue: c0,c1 -> (row, 2tg..2tg+1), c2,c3 -> (row+8, same cols)
#pragma unroll
    for (int mi = 0; mi < 2; ++mi) {
#pragma unroll
        for (int ni = 0; ni < 8; ++ni) {
            int row = rowBase + wm * 32 + mi * 16 + g;
            int col = nBase + wn * 64 + ni * 8 + 2 * tg;
            float bias0 = b2[col] + bd2[col];
            float bias1 = b2[col + 1] + bd2[col + 1];
            float2 o0 = make_float2(acc[mi][ni][0] + bias0,
                                    acc[mi][ni][1] + bias1);
            float2 o1 = make_float2(acc[mi][ni][2] + bias0,
                                    acc[mi][ni][3] + bias1);
            *(float2*)&out[(size_t)row * HID + col]       = o0;
            *(float2*)&out[(size_t)(row + 8) * HID + col] = o1;
        }
    }
}

// ---------------------------------------------------------------------------
extern "C" void kernel_launch(void* const* d_in, const int* in_sizes, int n_in,
                              void* d_out, int out_size) {
    (void)in_sizes; (void)n_in; (void)out_size;
    const float2* coords = (const float2*)d_in[0];
    const float*  W1  = (const float*)d_in[1];
    const float*  b1  = (const float*)d_in[2];
    const float*  W2  = (const float*)d_in[3];
    const float*  b2  = (const float*)d_in[4];
    const float*  Wd1 = (const float*)d_in[5];
    const float*  bd1 = (const float*)d_in[6];
    const float*  Wd2 = (const float*)d_in[7];
    const float*  bd2 = (const float*)d_in[8];
    float* out = (float*)d_out;

    count_and_convB<<<16 + 96, 1024>>>(coords, W2, Wd2);
    scan_counts<<<1, 1024>>>();
    scatter_pts<<<NPTS / 1024, 1024>>>(coords);
    query_and_buildA<<<NPTS / 8, 256>>>(W1, b1, Wd1, bd1);
    gemm_mma<<<dim3(2, 128), 256>>>(b2, bd2, out);
}